// round 5
// baseline (speedup 1.0000x reference)
#include <cuda_runtime.h>
#include <math.h>

#define BATCH   8
#define CH      512
#define HWDIM   64

__device__ float g_s [BATCH * CH];   // modulation scales s[b][i]
__device__ float g_w2[CH * CH];      // W2[o][i] = sum_k w[o][i][k]^2
__device__ float g_dm[BATCH * CH];   // CONV_SCALE * demod[b][o]

static __device__ __forceinline__ float warp_sum(float p) {
#pragma unroll
    for (int o = 16; o; o >>= 1) p += __shfl_xor_sync(0xffffffffu, p, o);
    return p;
}

#define MOD_SCALE  0.04419417382415922f     // 1/sqrt(512)
#define CONV_SCALE 0.014731391274719738f    // 1/sqrt(512*9)

// s[b][i] = MOD_SCALE * (style[b] . mod_weight[i]) + mod_bias[i]
__global__ void k_style(const float* __restrict__ style,
                        const float* __restrict__ mw,
                        const float* __restrict__ mb) {
    int W = blockIdx.x * 8 + (threadIdx.x >> 5);
    int lane = threadIdx.x & 31;
    int b = W >> 9, i = W & 511;
    const float* st = style + b * 512;
    const float* mr = mw + (size_t)i * 512;
    float p = 0.f;
#pragma unroll 4
    for (int d = lane; d < 512; d += 32) p += st[d] * mr[d];
    p = warp_sum(p);
    if (lane == 0) g_s[b * 512 + i] = p * MOD_SCALE + mb[i];
}

__global__ void k_w2(const float* __restrict__ w) {
    int idx = blockIdx.x * blockDim.x + threadIdx.x;   // o*512 + i
    const float* p = w + (size_t)idx * 9;
    float acc = 0.f;
#pragma unroll
    for (int k = 0; k < 9; k++) acc += p[k] * p[k];
    g_w2[idx] = acc;
}

__global__ void k_demod() {
    int W = blockIdx.x * 8 + (threadIdx.x >> 5);
    int lane = threadIdx.x & 31;
    int b = W >> 9, o = W & 511;
    float p = 0.f;
#pragma unroll 4
    for (int i = lane; i < 512; i += 32) {
        float sv = g_s[b * 512 + i];
        p += g_w2[o * 512 + i] * sv * sv;
    }
    p = warp_sum(p);
    if (lane == 0)
        g_dm[b * 512 + o] = CONV_SCALE * rsqrtf(CONV_SCALE * CONV_SCALE * p + 1e-8f);
}

// ---------------------------------------------------------------------------
// Main conv: per CTA = (batch b, 64 out-ch, 16x16 spatial tile).
// Input scaled by s[b][ic] on SMEM fill; pixels pre-paired across rows
// (r, r+8) as float2 so packed fma.rn.f32x2 needs no per-tap repacking.
// Weights stored to SMEM duplicated (w,w) -> warp-uniform LDS.64 broadcasts.
// ---------------------------------------------------------------------------
__global__ void __launch_bounds__(256, 2) k_conv(
    const float* __restrict__ x, const float* __restrict__ w,
    float* __restrict__ out)
{
    __shared__ __align__(16) float2 ws[64 * 72];      // [oc][icl*9 + k] dup halves
    __shared__ __align__(16) float2 xs[8 * 10 * 18];  // [icl][pairrow][col] (lo=r, hi=r+8)

    const int b   = blockIdx.z;
    const int ocb = blockIdx.y << 6;
    const int tr  = (blockIdx.x >> 2) << 4;
    const int tc  = (blockIdx.x & 3)  << 4;
    const int tid = threadIdx.x;
    const int og  = tid >> 5;          // warp = out-channel group (8 oc)
    const int lane = tid & 31;
    const int R   = lane >> 2;         // row-pair base 0..7 (rows R and R+8)
    const int cg  = lane & 3;          // 4 consecutive output cols

    unsigned long long acc[8][4];
#pragma unroll
    for (int oc = 0; oc < 8; oc++)
#pragma unroll
        for (int c = 0; c < 4; c++) acc[oc][c] = 0ull;

    const float* xb = x + (size_t)b * (CH * HWDIM * HWDIM);
    const float* sb = g_s + b * 512;

    for (int ic0 = 0; ic0 < 512; ic0 += 8) {
        __syncthreads();

        // ---- weights: coalesced global read (r fast), conflict-free STS ----
        {
            int oc = tid / 72;
            int r  = tid - oc * 72;
#pragma unroll
            for (int t = 0; t < 18; t++) {            // 64*72 = 18*256
                float v = w[(size_t)(ocb + oc) * 4608 + ic0 * 9 + r];
                ws[oc * 72 + r] = make_float2(v, v);
                r += 40; oc += 3;                     // advance by 256 = 3*72+40
                if (r >= 72) { r -= 72; oc++; }
            }
        }

        // ---- input tile: 8 ic x 18x18 halo, scaled, row-pair packed ----
#pragma unroll
        for (int t = 0; t < 6; t++) {
            int idx = tid + t * 256;
            if (idx < 1440) {                          // 8*10*18
                int icl = idx / 180;
                int rem = idx - icl * 180;
                int pr  = rem / 18;
                int c   = rem - pr * 18;
                float sc = sb[ic0 + icl];
                int col = tc - 1 + c;
                float lo = 0.f, hi = 0.f;
                if ((unsigned)col < 64u) {
                    const float* xp = xb + ((size_t)(ic0 + icl) << 12) + col;
                    int row = tr - 1 + pr;
                    if ((unsigned)row < 64u) lo = xp[row << 6] * sc;
                    row += 8;
                    if ((unsigned)row < 64u) hi = xp[row << 6] * sc;
                }
                xs[idx] = make_float2(lo, hi);
            }
        }
        __syncthreads();

        // ---- compute: 8 ic x 3 ky x 3 kx x 8 oc x 4 col-pairs ----
        for (int icl = 0; icl < 8; icl++) {
#pragma unroll
            for (int ky = 0; ky < 3; ky++) {
                const float2* xr = &xs[(icl * 10 + R + ky) * 18 + (cg << 2)];
                ulonglong2 t0 = *reinterpret_cast<const ulonglong2*>(xr);
                ulonglong2 t1 = *reinterpret_cast<const ulonglong2*>(xr + 2);
                ulonglong2 t2 = *reinterpret_cast<const ulonglong2*>(xr + 4);
                unsigned long long xv[6] = {t0.x, t0.y, t1.x, t1.y, t2.x, t2.y};
                const unsigned long long* wb =
                    reinterpret_cast<const unsigned long long*>(ws)
                    + og * (8 * 72) + icl * 9 + ky * 3;
#pragma unroll
                for (int kx = 0; kx < 3; kx++) {
#pragma unroll
                    for (int oc = 0; oc < 8; oc++) {
                        unsigned long long wv = wb[oc * 72 + kx];
#pragma unroll
                        for (int c = 0; c < 4; c++)
                            asm("fma.rn.f32x2 %0, %1, %2, %0;"
                                : "+l"(acc[oc][c]) : "l"(wv), "l"(xv[kx + c]));
                    }
                }
            }
        }
    }

    // ---- epilogue: scale by demod, vectorized 16B stores ----
    const int obase = ocb + (og << 3);
    size_t off = ((size_t)(b * 512 + obase) * 64 + (tr + R)) * 64 + tc + (cg << 2);
#pragma unroll
    for (int oc = 0; oc < 8; oc++) {
        float dm = g_dm[b * 512 + obase + oc];
        float4 vlo, vhi;
        vlo.x = __uint_as_float((unsigned)(acc[oc][0]        )) * dm;
        vlo.y = __uint_as_float((unsigned)(acc[oc][1]        )) * dm;
        vlo.z = __uint_as_float((unsigned)(acc[oc][2]        )) * dm;
        vlo.w = __uint_as_float((unsigned)(acc[oc][3]        )) * dm;
        vhi.x = __uint_as_float((unsigned)(acc[oc][0] >> 32  )) * dm;
        vhi.y = __uint_as_float((unsigned)(acc[oc][1] >> 32  )) * dm;
        vhi.z = __uint_as_float((unsigned)(acc[oc][2] >> 32  )) * dm;
        vhi.w = __uint_as_float((unsigned)(acc[oc][3] >> 32  )) * dm;
        float* p = out + off + (size_t)oc * 4096;
        *reinterpret_cast<float4*>(p)       = vlo;   // row tr+R
        *reinterpret_cast<float4*>(p + 512) = vhi;   // row tr+R+8
    }
}

extern "C" void kernel_launch(void* const* d_in, const int* in_sizes, int n_in,
                              void* d_out, int out_size) {
    const float* input  = (const float*)d_in[0];   // [8,512,64,64]
    const float* style  = (const float*)d_in[1];   // [8,512]
    const float* weight = (const float*)d_in[2];   // [1,512,512,3,3]
    const float* mod_w  = (const float*)d_in[3];   // [512,512]
    const float* mod_b  = (const float*)d_in[4];   // [512]
    float* out = (float*)d_out;                    // [8,512,64,64]

    k_style<<<512, 256>>>(style, mod_w, mod_b);    // 4096 warps
    k_w2   <<<1024, 256>>>(weight);                // 262144 threads
    k_demod<<<512, 256>>>();                       // 4096 warps
    dim3 grid(16, 8, 8);                           // (spatial 4x4, oc/64, batch)
    k_conv <<<grid, 256>>>(input, weight, out);
}

// round 6
// speedup vs baseline: 1.0011x; 1.0011x over previous
#include <cuda_runtime.h>
#include <math.h>

#define BATCH   8
#define CH      512
#define HWDIM   64

__device__ float g_s [BATCH * CH];   // modulation scales s[b][i]
__device__ float g_w2[CH * CH];      // W2[o][i] = sum_k w[o][i][k]^2
__device__ float g_dm[BATCH * CH];   // CONV_SCALE * demod[b][o]

static __device__ __forceinline__ float warp_sum(float p) {
#pragma unroll
    for (int o = 16; o; o >>= 1) p += __shfl_xor_sync(0xffffffffu, p, o);
    return p;
}

#define MOD_SCALE  0.04419417382415922f     // 1/sqrt(512)
#define CONV_SCALE 0.014731391274719738f    // 1/sqrt(512*9)

// s[b][i] = MOD_SCALE * (style[b] . mod_weight[i]) + mod_bias[i]
__global__ void k_style(const float* __restrict__ style,
                        const float* __restrict__ mw,
                        const float* __restrict__ mb) {
    int W = blockIdx.x * 8 + (threadIdx.x >> 5);
    int lane = threadIdx.x & 31;
    int b = W >> 9, i = W & 511;
    const float* st = style + b * 512;
    const float* mr = mw + (size_t)i * 512;
    float p = 0.f;
#pragma unroll 4
    for (int d = lane; d < 512; d += 32) p += st[d] * mr[d];
    p = warp_sum(p);
    if (lane == 0) g_s[b * 512 + i] = p * MOD_SCALE + mb[i];
}

__global__ void k_w2(const float* __restrict__ w) {
    int idx = blockIdx.x * blockDim.x + threadIdx.x;   // o*512 + i
    const float* p = w + (size_t)idx * 9;
    float acc = 0.f;
#pragma unroll
    for (int k = 0; k < 9; k++) acc += p[k] * p[k];
    g_w2[idx] = acc;
}

__global__ void k_demod() {
    int W = blockIdx.x * 8 + (threadIdx.x >> 5);
    int lane = threadIdx.x & 31;
    int b = W >> 9, o = W & 511;
    float p = 0.f;
#pragma unroll 4
    for (int i = lane; i < 512; i += 32) {
        float sv = g_s[b * 512 + i];
        p += g_w2[o * 512 + i] * sv * sv;
    }
    p = warp_sum(p);
    if (lane == 0)
        g_dm[b * 512 + o] = CONV_SCALE * rsqrtf(CONV_SCALE * CONV_SCALE * p + 1e-8f);
}

// ---------------------------------------------------------------------------
// Main conv: per CTA = (batch b, 64 out-ch, 16x16 spatial tile).
// Input scaled by s[b][ic] on SMEM fill; pixels pre-paired across rows
// (r, r+8) as float2 so packed fma.rn.f32x2 needs no per-tap repacking.
// Weights stored to SMEM duplicated (w,w) -> warp-uniform LDS.64 broadcasts.
// ---------------------------------------------------------------------------
__global__ void __launch_bounds__(256, 2) k_conv(
    const float* __restrict__ x, const float* __restrict__ w,
    float* __restrict__ out)
{
    __shared__ __align__(16) float2 ws[64 * 72];      // [oc][icl*9 + k] dup halves
    __shared__ __align__(16) float2 xs[8 * 10 * 18];  // [icl][pairrow][col] (lo=r, hi=r+8)

    const int b   = blockIdx.z;
    const int ocb = blockIdx.y << 6;
    const int tr  = (blockIdx.x >> 2) << 4;
    const int tc  = (blockIdx.x & 3)  << 4;
    const int tid = threadIdx.x;
    const int og  = tid >> 5;          // warp = out-channel group (8 oc)
    const int lane = tid & 31;
    const int R   = lane >> 2;         // row-pair base 0..7 (rows R and R+8)
    const int cg  = lane & 3;          // 4 consecutive output cols

    unsigned long long acc[8][4];
#pragma unroll
    for (int oc = 0; oc < 8; oc++)
#pragma unroll
        for (int c = 0; c < 4; c++) acc[oc][c] = 0ull;

    const float* xb = x + (size_t)b * (CH * HWDIM * HWDIM);
    const float* sb = g_s + b * 512;

    for (int ic0 = 0; ic0 < 512; ic0 += 8) {
        __syncthreads();

        // ---- weights: coalesced global read (r fast), conflict-free STS ----
        {
            int oc = tid / 72;
            int r  = tid - oc * 72;
#pragma unroll
            for (int t = 0; t < 18; t++) {            // 64*72 = 18*256
                float v = w[(size_t)(ocb + oc) * 4608 + ic0 * 9 + r];
                ws[oc * 72 + r] = make_float2(v, v);
                r += 40; oc += 3;                     // advance by 256 = 3*72+40
                if (r >= 72) { r -= 72; oc++; }
            }
        }

        // ---- input tile: 8 ic x 18x18 halo, scaled, row-pair packed ----
#pragma unroll
        for (int t = 0; t < 6; t++) {
            int idx = tid + t * 256;
            if (idx < 1440) {                          // 8*10*18
                int icl = idx / 180;
                int rem = idx - icl * 180;
                int pr  = rem / 18;
                int c   = rem - pr * 18;
                float sc = sb[ic0 + icl];
                int col = tc - 1 + c;
                float lo = 0.f, hi = 0.f;
                if ((unsigned)col < 64u) {
                    const float* xp = xb + ((size_t)(ic0 + icl) << 12) + col;
                    int row = tr - 1 + pr;
                    if ((unsigned)row < 64u) lo = xp[row << 6] * sc;
                    row += 8;
                    if ((unsigned)row < 64u) hi = xp[row << 6] * sc;
                }
                xs[idx] = make_float2(lo, hi);
            }
        }
        __syncthreads();

        // ---- compute: 8 ic x 3 ky x 3 kx x 8 oc x 4 col-pairs ----
        for (int icl = 0; icl < 8; icl++) {
#pragma unroll
            for (int ky = 0; ky < 3; ky++) {
                const float2* xr = &xs[(icl * 10 + R + ky) * 18 + (cg << 2)];
                ulonglong2 t0 = *reinterpret_cast<const ulonglong2*>(xr);
                ulonglong2 t1 = *reinterpret_cast<const ulonglong2*>(xr + 2);
                ulonglong2 t2 = *reinterpret_cast<const ulonglong2*>(xr + 4);
                unsigned long long xv[6] = {t0.x, t0.y, t1.x, t1.y, t2.x, t2.y};
                const unsigned long long* wb =
                    reinterpret_cast<const unsigned long long*>(ws)
                    + og * (8 * 72) + icl * 9 + ky * 3;
#pragma unroll
                for (int kx = 0; kx < 3; kx++) {
#pragma unroll
                    for (int oc = 0; oc < 8; oc++) {
                        unsigned long long wv = wb[oc * 72 + kx];
#pragma unroll
                        for (int c = 0; c < 4; c++)
                            asm("fma.rn.f32x2 %0, %1, %2, %0;"
                                : "+l"(acc[oc][c]) : "l"(wv), "l"(xv[kx + c]));
                    }
                }
            }
        }
    }

    // ---- epilogue: scale by demod, vectorized 16B stores ----
    const int obase = ocb + (og << 3);
    size_t off = ((size_t)(b * 512 + obase) * 64 + (tr + R)) * 64 + tc + (cg << 2);
#pragma unroll
    for (int oc = 0; oc < 8; oc++) {
        float dm = g_dm[b * 512 + obase + oc];
        float4 vlo, vhi;
        vlo.x = __uint_as_float((unsigned)(acc[oc][0]        )) * dm;
        vlo.y = __uint_as_float((unsigned)(acc[oc][1]        )) * dm;
        vlo.z = __uint_as_float((unsigned)(acc[oc][2]        )) * dm;
        vlo.w = __uint_as_float((unsigned)(acc[oc][3]        )) * dm;
        vhi.x = __uint_as_float((unsigned)(acc[oc][0] >> 32  )) * dm;
        vhi.y = __uint_as_float((unsigned)(acc[oc][1] >> 32  )) * dm;
        vhi.z = __uint_as_float((unsigned)(acc[oc][2] >> 32  )) * dm;
        vhi.w = __uint_as_float((unsigned)(acc[oc][3] >> 32  )) * dm;
        float* p = out + off + (size_t)oc * 4096;
        *reinterpret_cast<float4*>(p)       = vlo;   // row tr+R
        *reinterpret_cast<float4*>(p + 512) = vhi;   // row tr+R+8
    }
}

extern "C" void kernel_launch(void* const* d_in, const int* in_sizes, int n_in,
                              void* d_out, int out_size) {
    const float* input  = (const float*)d_in[0];   // [8,512,64,64]
    const float* style  = (const float*)d_in[1];   // [8,512]
    const float* weight = (const float*)d_in[2];   // [1,512,512,3,3]
    const float* mod_w  = (const float*)d_in[3];   // [512,512]
    const float* mod_b  = (const float*)d_in[4];   // [512]
    float* out = (float*)d_out;                    // [8,512,64,64]

    k_style<<<512, 256>>>(style, mod_w, mod_b);    // 4096 warps
    k_w2   <<<1024, 256>>>(weight);                // 262144 threads
    k_demod<<<512, 256>>>();                       // 4096 warps
    dim3 grid(16, 8, 8);                           // (spatial 4x4, oc/64, batch)
    k_conv <<<grid, 256>>>(input, weight, out);
}

// round 8
// speedup vs baseline: 3.5859x; 3.5819x over previous
#include <cuda_runtime.h>
#include <cuda_bf16.h>
#include <cstdint>

#define MOD_SCALE  0.04419417382415922f     // 1/sqrt(512)
#define CONV_SCALE 0.014731391274719738f    // 1/sqrt(512*9)

// ------------------------- device scratch (no allocs) ----------------------
__device__ float g_s [8*512];
__device__ float g_w2[512*512];
__device__ float g_dm[8*512];
__device__ __align__(16) __nv_bfloat16 g_wh[9*512*512];
__device__ __align__(16) __nv_bfloat16 g_wl[9*512*512];
__device__ __align__(16) __nv_bfloat16 g_xh[(size_t)8*66*66*512];
__device__ __align__(16) __nv_bfloat16 g_xl[(size_t)8*66*66*512];

// ------------------------- helpers -----------------------------------------
static __device__ __forceinline__ uint32_t smem_u32(const void* p) {
    uint32_t a;
    asm("{ .reg .u64 t; cvta.to.shared.u64 t, %1; cvt.u32.u64 %0, t; }"
        : "=r"(a) : "l"(p));
    return a;
}
#define CP16(dst, src) \
    asm volatile("cp.async.cg.shared.global [%0], [%1], 16;" :: "r"(dst), "l"(src))
#define CP_COMMIT() asm volatile("cp.async.commit_group;" ::: "memory")
#define CP_WAIT(n)  asm volatile("cp.async.wait_group %0;" :: "n"(n) : "memory")

#define SWZ(o) ((o) ^ (((o) >> 3) & 0x70))

static __device__ __forceinline__ void ldsm4(uint32_t* r, uint32_t addr) {
    asm volatile("ldmatrix.sync.aligned.m8n8.x4.shared.b16 {%0,%1,%2,%3}, [%4];"
                 : "=r"(r[0]), "=r"(r[1]), "=r"(r[2]), "=r"(r[3]) : "r"(addr));
}
static __device__ __forceinline__ void mma16816(float* c, const uint32_t* a,
                                                const uint32_t* b) {
    asm volatile(
        "mma.sync.aligned.m16n8k16.row.col.f32.bf16.bf16.f32 "
        "{%0,%1,%2,%3}, {%4,%5,%6,%7}, {%8,%9}, {%0,%1,%2,%3};"
        : "+f"(c[0]), "+f"(c[1]), "+f"(c[2]), "+f"(c[3])
        : "r"(a[0]), "r"(a[1]), "r"(a[2]), "r"(a[3]), "r"(b[0]), "r"(b[1]));
}

// ------------------------- prep kernels ------------------------------------
static __device__ __forceinline__ float warp_sum(float p) {
#pragma unroll
    for (int o = 16; o; o >>= 1) p += __shfl_xor_sync(0xffffffffu, p, o);
    return p;
}

__global__ void k_style(const float* __restrict__ style, const float* __restrict__ mw,
                        const float* __restrict__ mb) {
    int W = blockIdx.x * 8 + (threadIdx.x >> 5), lane = threadIdx.x & 31;
    int b = W >> 9, i = W & 511;
    const float* st = style + b * 512;
    const float* mr = mw + (size_t)i * 512;
    float p = 0.f;
#pragma unroll 4
    for (int d = lane; d < 512; d += 32) p += st[d] * mr[d];
    p = warp_sum(p);
    if (lane == 0) g_s[b * 512 + i] = p * MOD_SCALE + mb[i];
}

__global__ void k_w2(const float* __restrict__ w) {
    int idx = blockIdx.x * blockDim.x + threadIdx.x;
    const float* p = w + (size_t)idx * 9;
    float acc = 0.f;
#pragma unroll
    for (int k = 0; k < 9; k++) acc += p[k] * p[k];
    g_w2[idx] = acc;
}

__global__ void k_demod() {
    int W = blockIdx.x * 8 + (threadIdx.x >> 5), lane = threadIdx.x & 31;
    int b = W >> 9, o = W & 511;
    float p = 0.f;
#pragma unroll 4
    for (int i = lane; i < 512; i += 32) {
        float sv = g_s[b * 512 + i];
        p += g_w2[o * 512 + i] * sv * sv;
    }
    p = warp_sum(p);
    if (lane == 0)
        g_dm[b * 512 + o] = CONV_SCALE * rsqrtf(CONV_SCALE * CONV_SCALE * p + 1e-8f);
}

// split weights: g_w{h,l}[tap][o][i]
__global__ void k_wsplit(const float* __restrict__ w) {
    int idx = blockIdx.x * blockDim.x + threadIdx.x;   // o*512 + i
    const float* p = w + (size_t)idx * 9;
#pragma unroll
    for (int t = 0; t < 9; t++) {
        float v = p[t];
        __nv_bfloat16 h = __float2bfloat16(v);
        g_wh[(size_t)t * 262144 + idx] = h;
        g_wl[(size_t)t * 262144 + idx] = __float2bfloat16(v - __bfloat162float(h));
    }
}

// padded+transposed+scaled+split input: g_x{h,l}[b][r][c][ic], r,c in [0,66)
__global__ void k_xsplit(const float* __restrict__ x) {
    __shared__ float t[64][65];
    int r = blockIdx.x + 1, icc = blockIdx.y, b = blockIdx.z;
    int tx = threadIdx.x, ty = threadIdx.y;
    const float* xp = x + (((size_t)(b * 512 + icc * 64)) << 12) + ((r - 1) << 6);
#pragma unroll
    for (int k = 0; k < 8; k++) {
        int icl = ty + k * 8;
        float2 v = *(const float2*)(xp + ((size_t)icl << 12) + tx * 2);
        t[icl][tx * 2] = v.x; t[icl][tx * 2 + 1] = v.y;
    }
    __syncthreads();
    int ic = icc * 64 + 2 * tx;
    float s0 = g_s[b * 512 + ic], s1 = g_s[b * 512 + ic + 1];
#pragma unroll
    for (int k = 0; k < 8; k++) {
        int c = ty + k * 8;
        size_t o = ((size_t)(b * 66 + r) * 66 + (c + 1)) * 512 + ic;
        float v0 = t[2 * tx][c] * s0, v1 = t[2 * tx + 1][c] * s1;
        __nv_bfloat16 h0 = __float2bfloat16(v0), h1 = __float2bfloat16(v1);
        __nv_bfloat16 l0 = __float2bfloat16(v0 - __bfloat162float(h0));
        __nv_bfloat16 l1 = __float2bfloat16(v1 - __bfloat162float(h1));
        *(__nv_bfloat162*)(g_xh + o) = __halves2bfloat162(h0, h1);
        *(__nv_bfloat162*)(g_xl + o) = __halves2bfloat162(l0, l1);
    }
}

__global__ void k_xborder() {                 // zero the pad ring
    int i = blockIdx.x % 260, b = blockIdx.x / 260;
    int r, c;
    if      (i < 66)  { r = 0;        c = i;        }
    else if (i < 132) { r = 65;       c = i - 66;   }
    else if (i < 196) { r = i - 131;  c = 0;        }
    else              { r = i - 195;  c = 65;       }
    size_t o = ((size_t)(b * 66 + r) * 66 + c) * 512 + threadIdx.x * 2;
    __nv_bfloat162 z = __halves2bfloat162(__float2bfloat16(0.f), __float2bfloat16(0.f));
    *(__nv_bfloat162*)(g_xh + o) = z;
    *(__nv_bfloat162*)(g_xl + o) = z;
}

// ------------------------- main mma.sync conv -------------------------------
// CTA: M=128 oc x N=128 pixels, 8 warps (warp tile 64x32).
// 72 stages (9 taps x 8 ic-chunks of 64). Stage buf = Ah|Al|Bh|Bl (4x16KB),
// double-buffered cp.async pipeline.
__global__ void __launch_bounds__(256, 1) k_mma(float* __restrict__ out) {
    extern __shared__ char dynsm[];

    const int tid = threadIdx.x, wid = tid >> 5, lane = tid & 31;
    const int b   = blockIdx.x >> 5;
    const int n0  = (blockIdx.x & 31) << 7;      // 128-pixel chunk (2 rows)
    const int ocb = blockIdx.y << 7;

    const uint32_t sb = (smem_u32(dynsm) + 1023u) & ~1023u;

    const int m_base = (wid & 1) << 6;           // 0 / 64
    const int n_base = (wid >> 1) << 5;          // 0..96

    float acc[4][4][4];
#pragma unroll
    for (int mt = 0; mt < 4; mt++)
#pragma unroll
        for (int nt = 0; nt < 4; nt++)
#pragma unroll
            for (int q = 0; q < 4; q++) acc[mt][nt][q] = 0.f;

    // fill one stage's 4 tiles: 4096 x 16B cp.async across 256 threads
    auto fill_stage = [&](int s) {
        const int tap = s >> 3, ic0 = (s & 7) << 6;
        const int dy = tap / 3, dx = tap - dy * 3;
        const uint32_t sbase = sb + ((s & 1) << 16);
#pragma unroll
        for (int it = 0; it < 16; it++) {
            const int id   = tid + (it << 8);
            const int tile = id >> 10;
            const int row  = (id >> 3) & 127;
            const int j    = id & 7;
            const uint32_t dst = sbase + (tile << 14) + SWZ((row << 7) + (j << 4));
            const char* src;
            if (tile < 2) {
                const __nv_bfloat16* g = tile ? g_wl : g_wh;
                src = (const char*)(g + (((size_t)(tap * 512 + ocb + row) << 9) + ic0))
                      + (j << 4);
            } else {
                const __nv_bfloat16* g = (tile == 2) ? g_xh : g_xl;
                const int pix = n0 + row;
                const int pr = (pix >> 6) + dy, pc = (pix & 63) + dx;
                src = (const char*)(g + ((((size_t)(b * 66 + pr) * 66 + pc) << 9) + ic0))
                      + (j << 4);
            }
            CP16(dst, src);
        }
        CP_COMMIT();
    };

    // per-thread ldmatrix address components
    const int la15 = lane & 15;
    const int aK   = lane & 16;                  // A: +16B for k8..15 matrices
    const int bRow = (lane & 7) + ((lane & 16) >> 1);   // B row within 16-row group
    const int bK   = (lane & 8) << 1;            // B: +16B for k8..15 matrices

    fill_stage(0);

#pragma unroll 1
    for (int s = 0; s < 72; s++) {
        if (s + 1 < 72) { fill_stage(s + 1); CP_WAIT(1); }
        else            { CP_WAIT(0); }
        __syncthreads();

        const uint32_t sbase = sb + ((s & 1) << 16);
        const uint32_t aHb = sbase, aLb = sbase + 16384;
        const uint32_t bHb = sbase + 32768, bLb = sbase + 49152;

#pragma unroll
        for (int ks = 0; ks < 4; ks++) {
            const int kb = ks << 5;              // 32B per k16 step
            uint32_t ah[4][4], al[4][4], bh[2][4], bl[2][4];
#pragma unroll
            for (int mt = 0; mt < 4; mt++) {
                const uint32_t off = SWZ(((m_base + (mt << 4) + la15) << 7) + kb + aK);
                ldsm4(ah[mt], aHb + off);
                ldsm4(al[mt], aLb + off);
            }
#pragma unroll
            for (int h = 0; h < 2; h++) {
                const uint32_t off = SWZ(((n_base + (h << 4) + bRow) << 7) + kb + bK);
                ldsm4(bh[h], bHb + off);
                ldsm4(bl[h], bLb + off);
            }
#pragma unroll
            for (int mt = 0; mt < 4; mt++)
#pragma unroll
                for (int nt = 0; nt < 4; nt++) {
                    float* c = acc[mt][nt];
                    const uint32_t* bhf = &bh[nt >> 1][(nt & 1) << 1];
                    const uint32_t* blf = &bl[nt >> 1][(nt & 1) << 1];
                    mma16816(c, ah[mt], bhf);   // Wh*Xh
                    mma16816(c, al[mt], bhf);   // Wl*Xh
                    mma16816(c, ah[mt], blf);   // Wh*Xl
                }
        }
        __syncthreads();
    }

    // epilogue: demod scale + float2 stores
    const int oc0  = ocb + m_base + (lane >> 2);
    const int pixb = n0 + n_base + ((lane & 3) << 1);
#pragma unroll
    for (int mt = 0; mt < 4; mt++) {
        const int ocr = oc0 + (mt << 4);
        const float dm0 = g_dm[b * 512 + ocr];
        const float dm1 = g_dm[b * 512 + ocr + 8];
        float* p0 = out + (((size_t)(b * 512 + ocr)) << 12);
        float* p1 = p0 + (8 << 12);
#pragma unroll
        for (int nt = 0; nt < 4; nt++) {
            const int px = pixb + (nt << 3);
            float2 v0 = make_float2(acc[mt][nt][0] * dm0, acc[mt][nt][1] * dm0);
            float2 v1 = make_float2(acc[mt][nt][2] * dm1, acc[mt][nt][3] * dm1);
            *(float2*)(p0 + px) = v0;
            *(float2*)(p1 + px) = v1;
        }
    }
}

// ------------------------- launch ------------------------------------------
extern "C" void kernel_launch(void* const* d_in, const int* in_sizes, int n_in,
                              void* d_out, int out_size) {
    const float* input  = (const float*)d_in[0];   // [8,512,64,64]
    const float* style  = (const float*)d_in[1];   // [8,512]
    const float* weight = (const float*)d_in[2];   // [1,512,512,3,3]
    const float* mod_w  = (const float*)d_in[3];   // [512,512]
    const float* mod_b  = (const float*)d_in[4];   // [512]
    float* out = (float*)d_out;                    // [8,512,64,64]

    const int SMEM_DYN = 2 * 65536 + 1024;
    cudaFuncSetAttribute(k_mma, cudaFuncAttributeMaxDynamicSharedMemorySize, SMEM_DYN);

    k_style  <<<512, 256>>>(style, mod_w, mod_b);
    k_w2     <<<1024, 256>>>(weight);
    k_demod  <<<512, 256>>>();
    k_wsplit <<<1024, 256>>>(weight);
    k_xsplit <<<dim3(64, 8, 8), dim3(32, 8)>>>(input);
    k_xborder<<<2080, 256>>>();
    k_mma    <<<dim3(256, 4, 1), 256, SMEM_DYN>>>(out);
}

// round 9
// speedup vs baseline: 9.6345x; 2.6868x over previous
#include <cuda_runtime.h>
#include <cuda_fp16.h>
#include <cstdint>

#define MOD_SCALE  0.04419417382415922f     // 1/sqrt(512)
#define CONV_SCALE 0.014731391274719738f    // 1/sqrt(512*9)

// ------------------------- device scratch (no allocs) ----------------------
__device__ float g_s [8*512];
__device__ float g_w2[512*512];
__device__ float g_dm[8*512];
__device__ __align__(16) __half g_wf[9*512*512];            // [tap][oc][ic]
__device__ __align__(16) __half g_xf[(size_t)8*66*66*512];  // [b][r][c][ic]

// ------------------------- helpers -----------------------------------------
static __device__ __forceinline__ uint32_t smem_u32(const void* p) {
    uint32_t a;
    asm("{ .reg .u64 t; cvta.to.shared.u64 t, %1; cvt.u32.u64 %0, t; }"
        : "=r"(a) : "l"(p));
    return a;
}
#define CP16(dst, src) \
    asm volatile("cp.async.cg.shared.global [%0], [%1], 16;" :: "r"(dst), "l"(src))
#define CP_COMMIT() asm volatile("cp.async.commit_group;" ::: "memory")
#define CP_WAIT(n)  asm volatile("cp.async.wait_group %0;" :: "n"(n) : "memory")

#define SWZ(o) ((o) ^ (((o) >> 3) & 0x70))

static __device__ __forceinline__ void ldsm4(uint32_t* r, uint32_t addr) {
    asm volatile("ldmatrix.sync.aligned.m8n8.x4.shared.b16 {%0,%1,%2,%3}, [%4];"
                 : "=r"(r[0]), "=r"(r[1]), "=r"(r[2]), "=r"(r[3]) : "r"(addr));
}
static __device__ __forceinline__ void mma16816(float* c, const uint32_t* a,
                                                const uint32_t* b) {
    asm volatile(
        "mma.sync.aligned.m16n8k16.row.col.f32.f16.f16.f32 "
        "{%0,%1,%2,%3}, {%4,%5,%6,%7}, {%8,%9}, {%0,%1,%2,%3};"
        : "+f"(c[0]), "+f"(c[1]), "+f"(c[2]), "+f"(c[3])
        : "r"(a[0]), "r"(a[1]), "r"(a[2]), "r"(a[3]), "r"(b[0]), "r"(b[1]));
}

// ------------------------- prep kernels ------------------------------------
static __device__ __forceinline__ float warp_sum(float p) {
#pragma unroll
    for (int o = 16; o; o >>= 1) p += __shfl_xor_sync(0xffffffffu, p, o);
    return p;
}

__global__ void k_style(const float* __restrict__ style, const float* __restrict__ mw,
                        const float* __restrict__ mb) {
    int W = blockIdx.x * 8 + (threadIdx.x >> 5), lane = threadIdx.x & 31;
    int b = W >> 9, i = W & 511;
    const float* st = style + b * 512;
    const float* mr = mw + (size_t)i * 512;
    float p = 0.f;
#pragma unroll 4
    for (int d = lane; d < 512; d += 32) p += st[d] * mr[d];
    p = warp_sum(p);
    if (lane == 0) g_s[b * 512 + i] = p * MOD_SCALE + mb[i];
}

__global__ void k_w2(const float* __restrict__ w) {
    int idx = blockIdx.x * blockDim.x + threadIdx.x;
    const float* p = w + (size_t)idx * 9;
    float acc = 0.f;
#pragma unroll
    for (int k = 0; k < 9; k++) acc += p[k] * p[k];
    g_w2[idx] = acc;
}

__global__ void k_demod() {
    int W = blockIdx.x * 8 + (threadIdx.x >> 5), lane = threadIdx.x & 31;
    int b = W >> 9, o = W & 511;
    float p = 0.f;
#pragma unroll 4
    for (int i = lane; i < 512; i += 32) {
        float sv = g_s[b * 512 + i];
        p += g_w2[o * 512 + i] * sv * sv;
    }
    p = warp_sum(p);
    if (lane == 0)
        g_dm[b * 512 + o] = CONV_SCALE * rsqrtf(CONV_SCALE * CONV_SCALE * p + 1e-8f);
}

// weights -> fp16, tap-major: g_wf[tap][o][i]
__global__ void k_wconv(const float* __restrict__ w) {
    int idx = blockIdx.x * blockDim.x + threadIdx.x;   // o*512 + i
    const float* p = w + (size_t)idx * 9;
#pragma unroll
    for (int t = 0; t < 9; t++)
        g_wf[(size_t)t * 262144 + idx] = __float2half_rn(p[t]);
}

// padded+transposed+scaled fp16 input: g_xf[b][r][c][ic], r,c in [0,66)
__global__ void k_xconv(const float* __restrict__ x) {
    __shared__ float t[64][65];
    int r = blockIdx.x + 1, icc = blockIdx.y, b = blockIdx.z;
    int tx = threadIdx.x, ty = threadIdx.y;
    const float* xp = x + (((size_t)(b * 512 + icc * 64)) << 12) + ((r - 1) << 6);
#pragma unroll
    for (int k = 0; k < 8; k++) {
        int icl = ty + k * 8;
        float2 v = *(const float2*)(xp + ((size_t)icl << 12) + tx * 2);
        t[icl][tx * 2] = v.x; t[icl][tx * 2 + 1] = v.y;
    }
    __syncthreads();
    int ic = icc * 64 + 2 * tx;
    float s0 = g_s[b * 512 + ic], s1 = g_s[b * 512 + ic + 1];
#pragma unroll
    for (int k = 0; k < 8; k++) {
        int c = ty + k * 8;
        size_t o = ((size_t)(b * 66 + r) * 66 + (c + 1)) * 512 + ic;
        *(__half2*)(g_xf + o) =
            __floats2half2_rn(t[2 * tx][c] * s0, t[2 * tx + 1][c] * s1);
    }
}

__global__ void k_xborder() {                 // zero the pad ring
    int i = blockIdx.x % 260, b = blockIdx.x / 260;
    int r, c;
    if      (i < 66)  { r = 0;        c = i;        }
    else if (i < 132) { r = 65;       c = i - 66;   }
    else if (i < 196) { r = i - 131;  c = 0;        }
    else              { r = i - 195;  c = 65;       }
    size_t o = ((size_t)(b * 66 + r) * 66 + c) * 512 + threadIdx.x * 2;
    *(__half2*)(g_xf + o) = __floats2half2_rn(0.f, 0.f);
}

// ------------------------- main mma.sync conv -------------------------------
// CTA: M=128 oc x N=128 pixels, 8 warps (warp tile 64x32), fp16 single-pass.
// 72 stages (9 taps x 8 ic-chunks of 64). Stage buf = A|B (2x16KB),
// double-buffered cp.async pipeline, 2 CTAs/SM.
__global__ void __launch_bounds__(256, 2) k_mma(float* __restrict__ out) {
    extern __shared__ char dynsm[];

    const int tid = threadIdx.x, wid = tid >> 5, lane = tid & 31;
    const int b   = blockIdx.x >> 5;
    const int n0  = (blockIdx.x & 31) << 7;      // 128-pixel chunk (2 rows)
    const int ocb = blockIdx.y << 7;

    const uint32_t sb = (smem_u32(dynsm) + 1023u) & ~1023u;

    const int m_base = (wid & 1) << 6;           // 0 / 64
    const int n_base = (wid >> 1) << 5;          // 0..96

    float acc[4][4][4];
#pragma unroll
    for (int mt = 0; mt < 4; mt++)
#pragma unroll
        for (int nt = 0; nt < 4; nt++)
#pragma unroll
            for (int q = 0; q < 4; q++) acc[mt][nt][q] = 0.f;

    // fill one stage's 2 tiles: 2048 x 16B cp.async across 256 threads
    auto fill_stage = [&](int s) {
        const int tap = s >> 3, ic0 = (s & 7) << 6;
        const int dy = tap / 3, dx = tap - dy * 3;
        const uint32_t sbase = sb + ((s & 1) << 15);
#pragma unroll
        for (int it = 0; it < 8; it++) {
            const int id   = tid + (it << 8);
            const int tile = id >> 10;
            const int row  = (id >> 3) & 127;
            const int j    = id & 7;
            const uint32_t dst = sbase + (tile << 14) + SWZ((row << 7) + (j << 4));
            const char* src;
            if (tile == 0) {
                src = (const char*)(g_wf + (((size_t)(tap * 512 + ocb + row) << 9) + ic0))
                      + (j << 4);
            } else {
                const int pix = n0 + row;
                const int pr = (pix >> 6) + dy, pc = (pix & 63) + dx;
                src = (const char*)(g_xf + ((((size_t)(b * 66 + pr) * 66 + pc) << 9) + ic0))
                      + (j << 4);
            }
            CP16(dst, src);
        }
        CP_COMMIT();
    };

    // per-thread ldmatrix address components
    const int la15 = lane & 15;
    const int aK   = lane & 16;                  // A: +16B for k8..15 matrices
    const int bRow = (lane & 7) + ((lane & 16) >> 1);   // B row within 16-row group
    const int bK   = (lane & 8) << 1;            // B: +16B for k8..15 matrices

    fill_stage(0);

#pragma unroll 1
    for (int s = 0; s < 72; s++) {
        if (s + 1 < 72) { fill_stage(s + 1); CP_WAIT(1); }
        else            { CP_WAIT(0); }
        __syncthreads();

        const uint32_t sbase = sb + ((s & 1) << 15);
        const uint32_t aHb = sbase, bHb = sbase + 16384;

#pragma unroll
        for (int ks = 0; ks < 4; ks++) {
            const int kb = ks << 5;              // 32B per k16 step
            uint32_t ah[4][4], bh[2][4];
#pragma unroll
            for (int mt = 0; mt < 4; mt++) {
                const uint32_t off = SWZ(((m_base + (mt << 4) + la15) << 7) + kb + aK);
                ldsm4(ah[mt], aHb + off);
            }
#pragma unroll
            for (int h = 0; h < 2; h++) {
                const uint32_t off = SWZ(((n_base + (h << 4) + bRow) << 7) + kb + bK);
                ldsm4(bh[h], bHb + off);
            }
#pragma unroll
            for (int mt = 0; mt < 4; mt++)
#pragma unroll
                for (int nt = 0; nt < 4; nt++)
                    mma16816(acc[mt][nt], ah[mt], &bh[nt >> 1][(nt & 1) << 1]);
        }
        __syncthreads();
    }

    // epilogue: demod scale + float2 stores
    const int oc0  = ocb + m_base + (lane >> 2);
    const int pixb = n0 + n_base + ((lane & 3) << 1);
#pragma unroll
    for (int mt = 0; mt < 4; mt++) {
        const int ocr = oc0 + (mt << 4);
        const float dm0 = g_dm[b * 512 + ocr];
        const float dm1 = g_dm[b * 512 + ocr + 8];
        float* p0 = out + (((size_t)(b * 512 + ocr)) << 12);
        float* p1 = p0 + (8 << 12);
#pragma unroll
        for (int nt = 0; nt < 4; nt++) {
            const int px = pixb + (nt << 3);
            *(float2*)(p0 + px) = make_float2(acc[mt][nt][0] * dm0, acc[mt][nt][1] * dm0);
            *(float2*)(p1 + px) = make_float2(acc[mt][nt][2] * dm1, acc[mt][nt][3] * dm1);
        }
    }
}

// ------------------------- launch ------------------------------------------
extern "C" void kernel_launch(void* const* d_in, const int* in_sizes, int n_in,
                              void* d_out, int out_size) {
    const float* input  = (const float*)d_in[0];   // [8,512,64,64]
    const float* style  = (const float*)d_in[1];   // [8,512]
    const float* weight = (const float*)d_in[2];   // [1,512,512,3,3]
    const float* mod_w  = (const float*)d_in[3];   // [512,512]
    const float* mod_b  = (const float*)d_in[4];   // [512]
    float* out = (float*)d_out;                    // [8,512,64,64]

    const int SMEM_DYN = 2 * 32768 + 1024;
    cudaFuncSetAttribute(k_mma, cudaFuncAttributeMaxDynamicSharedMemorySize, SMEM_DYN);

    k_style  <<<512, 256>>>(style, mod_w, mod_b);
    k_w2     <<<1024, 256>>>(weight);
    k_demod  <<<512, 256>>>();
    k_wconv  <<<1024, 256>>>(weight);
    k_xconv  <<<dim3(64, 8, 8), dim3(32, 8)>>>(input);
    k_xborder<<<2080, 256>>>();
    k_mma    <<<dim3(256, 4, 1), 256, SMEM_DYN>>>(out);
}